// round 5
// baseline (speedup 1.0000x reference)
#include <cuda_runtime.h>
#include <math.h>

// Problem constants
#define EDIM   128
#define LSEQ   512
#define NB     16
#define NFEAT  32
#define FBINS  8193
#define LAMBDA 0.01f

// Persistent scratch (device globals)
__device__ __align__(256) float2 d_X[NB][FBINS];   // forward spectrum (ortho)
__device__ __align__(256) float  d_H1[NB][EDIM * 8];
__device__ __align__(256) float  d_TA[FBINS][8];   // irfft+emb10 folded cos table
__device__ __align__(256) float  d_TB[FBINS][8];   // irfft+emb10 folded sin table

__device__ __forceinline__ float sshrink(float v) {
    return v > LAMBDA ? v - LAMBDA : (v < -LAMBDA ? v + LAMBDA : 0.0f);
}

__device__ __forceinline__ unsigned long long fma2(unsigned long long a,
                                                   unsigned long long b,
                                                   unsigned long long c) {
    unsigned long long d;
    asm("fma.rn.f32x2 %0, %1, %2, %3;" : "=l"(d) : "l"(a), "l"(b), "l"(c));
    return d;
}
__device__ __forceinline__ unsigned long long pack2(float v) {
    unsigned long long d;
    asm("mov.b64 %0, {%1, %1};" : "=l"(d) : "f"(v));
    return d;
}
__device__ __forceinline__ float2 unpack2(unsigned long long p) {
    float2 r;
    asm("mov.b64 {%0, %1}, %2;" : "=f"(r.x), "=f"(r.y) : "l"(p));
    return r;
}

// ---------------------------------------------------------------------------
// Kernel 1: PREP. Blocks 0..511: forward rfft (r = bi&31, b = bi>>5).
// Blocks 512..640: build TA/TB tables via integer-phase cos table.
// 512 threads, 48KB dynamic smem.
// ---------------------------------------------------------------------------
__global__ void __launch_bounds__(512)
prep(const float* __restrict__ x, const float* __restrict__ emb10) {
    extern __shared__ float sm[];
    const int bi  = blockIdx.x;
    const int tid = threadIdx.x;

    if (bi < 512) {
        // ---------------- forward rfft path ----------------
        float2* buf = (float2*)sm;          // 512 complex
        float2* tw  = buf + 512;            // 256 twiddles e^{-2pi i j/512}
        float2* w32 = tw + 256;             // 32 twiddles e^{-2pi i r q/32}
        const int r = bi & 31;
        const int b = bi >> 5;

        if (tid < 256) {
            float s, c;
            sincospif((float)tid * (1.0f / 256.0f), &s, &c);
            tw[tid] = make_float2(c, -s);
        } else if (tid < 288) {
            int q = tid - 256;
            int ph = (r * q) & 31;
            float s, c;
            sincospif((float)ph * (1.0f / 16.0f), &s, &c);
            w32[q] = make_float2(c, -s);
        }

        // load own row into registers (l = tid)
        const int l = tid;
        float4 xv4[8];
        const float4* xr4 = (const float4*)(x + (b * LSEQ + l) * NFEAT);
        #pragma unroll
        for (int i = 0; i < 8; i++) xv4[i] = xr4[i];
        __syncthreads();

        // 32-pt DFT over q + CT twiddle
        float sr = 0.0f, si = 0.0f;
        const float* xv = (const float*)xv4;
        #pragma unroll
        for (int q = 0; q < 32; q++) {
            float2 w = w32[q];
            sr = fmaf(xv[q], w.x, sr);
            si = fmaf(xv[q], w.y, si);
        }
        float ss, cc;
        sincospif((float)(r * l) * (1.0f / 8192.0f), &ss, &cc);
        float yr = fmaf(sr, cc,  si * ss);
        float yi = fmaf(si, cc, -sr * ss);
        buf[__brev((unsigned)l) >> 23] = make_float2(yr, yi);
        __syncthreads();

        // 512-pt DIT FFT (256 butterflies/stage)
        #pragma unroll
        for (int s = 0; s < 9; s++) {
            if (tid < 256) {
                int half = 1 << s;
                int j = tid & (half - 1);
                int i = ((tid >> s) << (s + 1)) + j;
                float2 w = tw[j << (8 - s)];
                float2 u = buf[i];
                float2 v = buf[i + half];
                float vr = v.x * w.x - v.y * w.y;
                float vi = v.x * w.y + v.y * w.x;
                buf[i]        = make_float2(u.x + vr, u.y + vi);
                buf[i + half] = make_float2(u.x - vr, u.y - vi);
            }
            __syncthreads();
        }

        if (tid < 256) {
            const float sc = 1.0f / 128.0f;
            #pragma unroll
            for (int k = 0; k < 2; k++) {
                int t = tid + 256 * k;
                int f = 32 * t + r;
                if (f <= 8192)
                    d_X[b][f] = make_float2(buf[t].x * sc, buf[t].y * sc);
            }
        }
    } else {
        // ---------------- TA/TB table path ----------------
        float* ctab = sm;            // 8192: cos(2pi k/16384), k<8192
        float* E    = sm + 8192;     // 4096: emb10
        #pragma unroll
        for (int i = 0; i < 16; i++) {
            int k = tid + 512 * i;
            ctab[k] = cospif((float)k * (1.0f / 8192.0f));
        }
        for (int i = tid; i < LSEQ * 8; i += 512) E[i] = emb10[i];
        __syncthreads();

        const int f = (bi - 512) * 64 + (tid >> 3);
        const int j = tid & 7;
        if (f > 8192) return;

        float a = 0.0f, bsum = 0.0f;
        int ph = 0;   // = (f*l) mod 16384
        for (int l = 0; l < LSEQ; l++) {
            int t  = ph & 8191;
            float cv = ctab[t];
            cv = (ph & 8192) ? -cv : cv;
            int q  = (ph - 4096) & 16383;
            float sv = ctab[q & 8191];
            sv = (q & 8192) ? -sv : sv;
            float ev = E[l * 8 + j];
            a    = fmaf(cv, ev, a);
            bsum = fmaf(sv, ev, bsum);
            ph = (ph + f) & 16383;
        }
        float sf = (f == 0 || f == 8192) ? (1.0f / 128.0f) : (2.0f / 128.0f);
        d_TA[f][j] =  sf * a;
        d_TB[f][j] = -sf * bsum;
    }
}

// ---------------------------------------------------------------------------
// Kernel 2: fused fourierGC + (irfft . emb10) contraction. Packed f32x2 accs.
// ---------------------------------------------------------------------------
__global__ void __launch_bounds__(256, 1)
gc_gemm(const float* __restrict__ emb,
        const float* __restrict__ w0, const float* __restrict__ b0,
        const float* __restrict__ w1, const float* __restrict__ b1,
        const float* __restrict__ w2, const float* __restrict__ b2) {
    const int e0 = blockIdx.x * 8;
    const int b  = blockIdx.y;
    const int tid = threadIdx.x;

    float D00[8], D01[8], C00[8], C01[8];
    float d10[8], d11[8], C10[8], C11[8];
    float d20[8], d21[8], C20[8], C21[8];
    #pragma unroll
    for (int eo = 0; eo < 8; eo++) {
        int e = e0 + eo;
        float em = emb[e];
        D00[eo] = em * w0[e * 129];  D01[eo] = em * w0[16384 + e * 129];
        C00[eo] = b0[e];             C01[eo] = b0[128 + e];
        d10[eo] = w1[e * 129];       d11[eo] = w1[16384 + e * 129];
        C10[eo] = b1[e];             C11[eo] = b1[128 + e];
        d20[eo] = w2[e * 129];       d21[eo] = w2[16384 + e * 129];
        C20[eo] = b2[e];             C21[eo] = b2[128 + e];
    }

    unsigned long long acc2[8][4];
    #pragma unroll
    for (int eo = 0; eo < 8; eo++)
        #pragma unroll
        for (int p = 0; p < 4; p++) acc2[eo][p] = 0ull;

    for (int f = tid; f < FBINS; f += 256) {
        float2 X = d_X[b][f];
        float xr = X.x, xi = X.y;
        const ulonglong2* taP = (const ulonglong2*)d_TA[f];
        const ulonglong2* tbP = (const ulonglong2*)d_TB[f];
        ulonglong2 taL = taP[0], taH = taP[1];
        ulonglong2 tbL = tbP[0], tbH = tbP[1];
        #pragma unroll
        for (int eo = 0; eo < 8; eo++) {
            float or1 = fmaxf(fmaf(xr, D00[eo], fmaf(-xi, D01[eo], C00[eo])), 0.0f);
            float oi1 = fmaxf(fmaf(xi, D00[eo], fmaf( xr, D01[eo], C01[eo])), 0.0f);
            float pr = sshrink(or1), pi = sshrink(oi1);
            float or2 = fmaxf(fmaf(or1, d10[eo], fmaf(-oi1, d11[eo], C10[eo])), 0.0f);
            float oi2 = fmaxf(fmaf(oi1, d10[eo], fmaf( or2, d11[eo], C11[eo])), 0.0f);
            pr += sshrink(or2); pi += sshrink(oi2);
            float or3 = fmaxf(fmaf(or2, d20[eo], fmaf(-oi2, d21[eo], C20[eo])), 0.0f);
            float oi3 = fmaxf(fmaf(oi2, d20[eo], fmaf( or3, d21[eo], C21[eo])), 0.0f);
            unsigned long long zr2 = pack2(sshrink(or3) + pr);
            unsigned long long zi2 = pack2(sshrink(oi3) + pi);
            acc2[eo][0] = fma2(zr2, taL.x, fma2(zi2, tbL.x, acc2[eo][0]));
            acc2[eo][1] = fma2(zr2, taL.y, fma2(zi2, tbL.y, acc2[eo][1]));
            acc2[eo][2] = fma2(zr2, taH.x, fma2(zi2, tbH.x, acc2[eo][2]));
            acc2[eo][3] = fma2(zr2, taH.y, fma2(zi2, tbH.y, acc2[eo][3]));
        }
    }

    __shared__ float red[8][64];
    const int lane = tid & 31, w = tid >> 5;
    #pragma unroll
    for (int eo = 0; eo < 8; eo++) {
        #pragma unroll
        for (int p = 0; p < 4; p++) {
            float2 pv = unpack2(acc2[eo][p]);
            #pragma unroll
            for (int o = 16; o; o >>= 1) {
                pv.x += __shfl_down_sync(0xFFFFFFFFu, pv.x, o);
                pv.y += __shfl_down_sync(0xFFFFFFFFu, pv.y, o);
            }
            if (lane == 0) {
                red[w][eo * 8 + 2 * p]     = pv.x;
                red[w][eo * 8 + 2 * p + 1] = pv.y;
            }
        }
    }
    __syncthreads();
    if (tid < 64) {
        float s = 0.0f;
        #pragma unroll
        for (int ww = 0; ww < 8; ww++) s += red[ww][tid];
        d_H1[b][e0 * 8 + tid] = s;
    }
}

// ---------------------------------------------------------------------------
// Kernel 3: bias projection + final MLP. 16 blocks x 512 threads.
// fc1: 8 thr/out, fc2: 2 thr/out, fc3: 4 thr/out.
// ---------------------------------------------------------------------------
__global__ void __launch_bounds__(512)
mlp_kernel(const float* __restrict__ x, const float* __restrict__ emb,
           const float* __restrict__ emb10,
           const float* __restrict__ fc1w, const float* __restrict__ fc1b,
           const float* __restrict__ fc2w, const float* __restrict__ fc2b,
           const float* __restrict__ fc3w, const float* __restrict__ fc3b,
           float* __restrict__ out) {
    __shared__ __align__(16) float h[1024];
    __shared__ __align__(16) float v1[64];
    __shared__ __align__(16) float v2[256];
    __shared__ float xs[LSEQ];
    __shared__ float Ps[8];
    const int b = blockIdx.x;
    const int tid = threadIdx.x;
    const int w = tid >> 5, lane = tid & 31;

    // P[b,j] = sum_l x[b,l,0] * emb10[l,j]
    xs[tid] = x[(b * LSEQ + tid) * NFEAT];
    __syncthreads();
    if (w < 8) {
        float s = 0.0f;
        #pragma unroll
        for (int i = 0; i < 16; i++)
            s += xs[lane + 32 * i] * emb10[(lane + 32 * i) * 8 + w];
        #pragma unroll
        for (int o = 16; o; o >>= 1) s += __shfl_down_sync(0xFFFFFFFFu, s, o);
        if (lane == 0) Ps[w] = s;
    }
    __syncthreads();

    // h = H1 + emb[e] * P[j]
    #pragma unroll
    for (int k = 0; k < 2; k++) {
        int i = tid + 512 * k;
        h[i] = d_H1[b][i] + emb[i >> 3] * Ps[i & 7];
    }
    __syncthreads();

    // fc1: 64 outputs, 8 threads each
    {
        const int j = tid >> 3, sub = tid & 7;
        const float4* fw = (const float4*)(fc1w + j * 1024);
        const float4* h4 = (const float4*)h;
        float s = 0.0f;
        #pragma unroll
        for (int i = 0; i < 32; i++) {
            float4 a = fw[sub + 8 * i];
            float4 v = h4[sub + 8 * i];
            s += a.x * v.x + a.y * v.y + a.z * v.z + a.w * v.w;
        }
        s += __shfl_down_sync(0xFFFFFFFFu, s, 4, 8);
        s += __shfl_down_sync(0xFFFFFFFFu, s, 2, 8);
        s += __shfl_down_sync(0xFFFFFFFFu, s, 1, 8);
        if (sub == 0) {
            s += fc1b[j];
            v1[j] = s > 0.0f ? s : 0.01f * s;
        }
    }
    __syncthreads();

    // fc2: 256 outputs, 2 threads each
    {
        const int j = tid >> 1, sub = tid & 1;
        const float4* fw = (const float4*)(fc2w + j * 64);
        const float4* v14 = (const float4*)v1;
        float s = 0.0f;
        #pragma unroll
        for (int i = 0; i < 8; i++) {
            float4 a = fw[sub * 8 + i];
            float4 v = v14[sub * 8 + i];
            s += a.x * v.x + a.y * v.y + a.z * v.z + a.w * v.w;
        }
        s += __shfl_down_sync(0xFFFFFFFFu, s, 1, 2);
        if (sub == 0) {
            s += fc2b[j];
            v2[j] = s > 0.0f ? s : 0.01f * s;
        }
    }
    __syncthreads();

    // fc3: 96 outputs, 4 threads each
    if (tid < 384) {
        const int j = tid >> 2, sub = tid & 3;
        const float4* fw = (const float4*)(fc3w + j * 256);
        const float4* v24 = (const float4*)v2;
        float s = 0.0f;
        #pragma unroll
        for (int i = 0; i < 16; i++) {
            float4 a = fw[sub * 16 + i];
            float4 v = v24[sub * 16 + i];
            s += a.x * v.x + a.y * v.y + a.z * v.z + a.w * v.w;
        }
        s += __shfl_down_sync(0xFFFFFFFFu, s, 2, 4);
        s += __shfl_down_sync(0xFFFFFFFFu, s, 1, 4);
        if (sub == 0) out[b * 96 + j] = s + fc3b[j];
    }
}

// ---------------------------------------------------------------------------
extern "C" void kernel_launch(void* const* d_in, const int* in_sizes, int n_in,
                              void* d_out, int out_size) {
    const float* x     = (const float*)d_in[0];
    const float* emb   = (const float*)d_in[1];
    const float* w0    = (const float*)d_in[2];
    const float* b0    = (const float*)d_in[3];
    const float* w1    = (const float*)d_in[4];
    const float* b1    = (const float*)d_in[5];
    const float* w2    = (const float*)d_in[6];
    const float* b2    = (const float*)d_in[7];
    const float* emb10 = (const float*)d_in[8];
    const float* fc1w  = (const float*)d_in[9];
    const float* fc1b  = (const float*)d_in[10];
    const float* fc2w  = (const float*)d_in[11];
    const float* fc2b  = (const float*)d_in[12];
    const float* fc3w  = (const float*)d_in[13];
    const float* fc3b  = (const float*)d_in[14];
    float* out = (float*)d_out;

    const int smem_prep = (8192 + 4096) * 4;   // 49152 (table path dominates)
    static bool attr_set = false;
    if (!attr_set) {
        cudaFuncSetAttribute(prep, cudaFuncAttributeMaxDynamicSharedMemorySize, smem_prep);
        attr_set = true;
    }

    prep<<<641, 512, smem_prep>>>(x, emb10);
    gc_gemm<<<dim3(EDIM / 8, NB), 256>>>(emb, w0, b0, w1, b1, w2, b2);
    mlp_kernel<<<NB, 512>>>(x, emb, emb10, fc1w, fc1b, fc2w, fc2b, fc3w, fc3b, out);
}

// round 6
// speedup vs baseline: 1.4425x; 1.4425x over previous
#include <cuda_runtime.h>
#include <math.h>

// Problem constants
#define EDIM   128
#define LSEQ   512
#define NB     16
#define NFEAT  32
#define FBINS  8193
#define LAMBDA 0.01f

// Persistent scratch (device globals)
__device__ __align__(256) float2 d_X[NB][FBINS];   // forward spectrum (ortho)
__device__ __align__(256) float  d_H1[NB][EDIM * 8];
__device__ __align__(256) float  d_TA[FBINS][8];   // irfft+emb10 folded cos table
__device__ __align__(256) float  d_TB[FBINS][8];   // irfft+emb10 folded sin table

__device__ __forceinline__ float sshrink(float v) {
    return v > LAMBDA ? v - LAMBDA : (v < -LAMBDA ? v + LAMBDA : 0.0f);
}

__device__ __forceinline__ unsigned long long fma2(unsigned long long a,
                                                   unsigned long long b,
                                                   unsigned long long c) {
    unsigned long long d;
    asm("fma.rn.f32x2 %0, %1, %2, %3;" : "=l"(d) : "l"(a), "l"(b), "l"(c));
    return d;
}
__device__ __forceinline__ unsigned long long pack2(float v) {
    unsigned long long d;
    asm("mov.b64 %0, {%1, %1};" : "=l"(d) : "f"(v));
    return d;
}
__device__ __forceinline__ float2 unpack2(unsigned long long p) {
    float2 r;
    asm("mov.b64 {%0, %1}, %2;" : "=f"(r.x), "=f"(r.y) : "l"(p));
    return r;
}

// ---------------------------------------------------------------------------
// Kernel 1: PREP. 768 uniform FFT blocks x 256 threads.
//   Blocks 0..511  : forward rfft. r = bi&31, b = bi>>5.
//   Blocks 512..767: TA/TB tables = zero-padded DFT of emb10 columns.
//                    idx = bi-512, r = idx&31, j = idx>>5.
// Both paths: pre-twiddle -> 512-pt DIT FFT over l -> scatter f = 32t + r.
// ---------------------------------------------------------------------------
__global__ void __launch_bounds__(256)
prep(const float* __restrict__ x, const float* __restrict__ emb10) {
    __shared__ float2 buf[512];
    __shared__ float2 tw[256];      // e^{-2pi i k/512}
    __shared__ float2 w32[32];      // e^{-2pi i r q/32} (fwd path only)
    const int bi  = blockIdx.x;
    const int tid = threadIdx.x;
    const bool fwd = (bi < 512);
    const int idx = fwd ? bi : bi - 512;
    const int r = idx & 31;

    {
        float s, c;
        sincospif((float)tid * (1.0f / 256.0f), &s, &c);
        tw[tid] = make_float2(c, -s);
    }
    if (fwd && tid < 32) {
        int ph = (r * tid) & 31;
        float s, c;
        sincospif((float)ph * (1.0f / 16.0f), &s, &c);
        w32[tid] = make_float2(c, -s);
    }
    __syncthreads();

    if (fwd) {
        const int b = idx >> 5;
        #pragma unroll
        for (int li = 0; li < 2; li++) {
            const int l = tid + 256 * li;
            // 32-pt DFT over features q for this l
            const float4* xr4 = (const float4*)(x + (b * LSEQ + l) * NFEAT);
            float sr = 0.0f, si = 0.0f;
            #pragma unroll
            for (int i = 0; i < 8; i++) {
                float4 v4 = xr4[i];
                float2 wa = w32[4 * i + 0], wb = w32[4 * i + 1];
                float2 wc = w32[4 * i + 2], wd = w32[4 * i + 3];
                sr = fmaf(v4.x, wa.x, sr); si = fmaf(v4.x, wa.y, si);
                sr = fmaf(v4.y, wb.x, sr); si = fmaf(v4.y, wb.y, si);
                sr = fmaf(v4.z, wc.x, sr); si = fmaf(v4.z, wc.y, si);
                sr = fmaf(v4.w, wd.x, sr); si = fmaf(v4.w, wd.y, si);
            }
            // CT twiddle e^{-2pi i r l / 16384}
            float ss, cc;
            sincospif((float)(r * l) * (1.0f / 8192.0f), &ss, &cc);
            float yr = fmaf(sr, cc,  si * ss);
            float yi = fmaf(si, cc, -sr * ss);
            buf[__brev((unsigned)l) >> 23] = make_float2(yr, yi);
        }
    } else {
        const int j = idx >> 5;
        #pragma unroll
        for (int li = 0; li < 2; li++) {
            const int l = tid + 256 * li;
            float ev = emb10[l * 8 + j];
            float ss, cc;
            sincospif((float)(r * l) * (1.0f / 8192.0f), &ss, &cc);
            buf[__brev((unsigned)l) >> 23] = make_float2(ev * cc, -ev * ss);
        }
    }
    __syncthreads();

    // 512-pt DIT FFT, 256 butterflies/stage
    #pragma unroll
    for (int s = 0; s < 9; s++) {
        int half = 1 << s;
        int jj = tid & (half - 1);
        int i = ((tid >> s) << (s + 1)) + jj;
        float2 w = tw[jj << (8 - s)];
        float2 u = buf[i];
        float2 v = buf[i + half];
        float vr = v.x * w.x - v.y * w.y;
        float vi = v.x * w.y + v.y * w.x;
        buf[i]        = make_float2(u.x + vr, u.y + vi);
        buf[i + half] = make_float2(u.x - vr, u.y - vi);
        __syncthreads();
    }

    if (fwd) {
        const int b = idx >> 5;
        const float sc = 1.0f / 128.0f;
        #pragma unroll
        for (int li = 0; li < 2; li++) {
            int t = tid + 256 * li;
            int f = 32 * t + r;
            if (f <= 8192)
                d_X[b][f] = make_float2(buf[t].x * sc, buf[t].y * sc);
        }
    } else {
        const int j = idx >> 5;
        #pragma unroll
        for (int li = 0; li < 2; li++) {
            int t = tid + 256 * li;
            int f = 32 * t + r;
            if (f <= 8192) {
                float sf = (f == 0 || f == 8192) ? (1.0f / 128.0f) : (2.0f / 128.0f);
                d_TA[f][j] = sf * buf[t].x;
                d_TB[f][j] = sf * buf[t].y;
            }
        }
    }
}

// ---------------------------------------------------------------------------
// Kernel 2: fused fourierGC + (irfft . emb10) contraction. Packed f32x2 accs.
// ---------------------------------------------------------------------------
__global__ void __launch_bounds__(256, 1)
gc_gemm(const float* __restrict__ emb,
        const float* __restrict__ w0, const float* __restrict__ b0,
        const float* __restrict__ w1, const float* __restrict__ b1,
        const float* __restrict__ w2, const float* __restrict__ b2) {
    const int e0 = blockIdx.x * 8;
    const int b  = blockIdx.y;
    const int tid = threadIdx.x;

    float D00[8], D01[8], C00[8], C01[8];
    float d10[8], d11[8], C10[8], C11[8];
    float d20[8], d21[8], C20[8], C21[8];
    #pragma unroll
    for (int eo = 0; eo < 8; eo++) {
        int e = e0 + eo;
        float em = emb[e];
        D00[eo] = em * w0[e * 129];  D01[eo] = em * w0[16384 + e * 129];
        C00[eo] = b0[e];             C01[eo] = b0[128 + e];
        d10[eo] = w1[e * 129];       d11[eo] = w1[16384 + e * 129];
        C10[eo] = b1[e];             C11[eo] = b1[128 + e];
        d20[eo] = w2[e * 129];       d21[eo] = w2[16384 + e * 129];
        C20[eo] = b2[e];             C21[eo] = b2[128 + e];
    }

    unsigned long long acc2[8][4];
    #pragma unroll
    for (int eo = 0; eo < 8; eo++)
        #pragma unroll
        for (int p = 0; p < 4; p++) acc2[eo][p] = 0ull;

    for (int f = tid; f < FBINS; f += 256) {
        float2 X = d_X[b][f];
        float xr = X.x, xi = X.y;
        const ulonglong2* taP = (const ulonglong2*)d_TA[f];
        const ulonglong2* tbP = (const ulonglong2*)d_TB[f];
        ulonglong2 taL = taP[0], taH = taP[1];
        ulonglong2 tbL = tbP[0], tbH = tbP[1];
        #pragma unroll
        for (int eo = 0; eo < 8; eo++) {
            float or1 = fmaxf(fmaf(xr, D00[eo], fmaf(-xi, D01[eo], C00[eo])), 0.0f);
            float oi1 = fmaxf(fmaf(xi, D00[eo], fmaf( xr, D01[eo], C01[eo])), 0.0f);
            float pr = sshrink(or1), pi = sshrink(oi1);
            float or2 = fmaxf(fmaf(or1, d10[eo], fmaf(-oi1, d11[eo], C10[eo])), 0.0f);
            float oi2 = fmaxf(fmaf(oi1, d10[eo], fmaf( or2, d11[eo], C11[eo])), 0.0f);
            pr += sshrink(or2); pi += sshrink(oi2);
            float or3 = fmaxf(fmaf(or2, d20[eo], fmaf(-oi2, d21[eo], C20[eo])), 0.0f);
            float oi3 = fmaxf(fmaf(oi2, d20[eo], fmaf( or3, d21[eo], C21[eo])), 0.0f);
            unsigned long long zr2 = pack2(sshrink(or3) + pr);
            unsigned long long zi2 = pack2(sshrink(oi3) + pi);
            acc2[eo][0] = fma2(zr2, taL.x, fma2(zi2, tbL.x, acc2[eo][0]));
            acc2[eo][1] = fma2(zr2, taL.y, fma2(zi2, tbL.y, acc2[eo][1]));
            acc2[eo][2] = fma2(zr2, taH.x, fma2(zi2, tbH.x, acc2[eo][2]));
            acc2[eo][3] = fma2(zr2, taH.y, fma2(zi2, tbH.y, acc2[eo][3]));
        }
    }

    __shared__ float red[8][64];
    const int lane = tid & 31, w = tid >> 5;
    #pragma unroll
    for (int eo = 0; eo < 8; eo++) {
        #pragma unroll
        for (int p = 0; p < 4; p++) {
            float2 pv = unpack2(acc2[eo][p]);
            #pragma unroll
            for (int o = 16; o; o >>= 1) {
                pv.x += __shfl_down_sync(0xFFFFFFFFu, pv.x, o);
                pv.y += __shfl_down_sync(0xFFFFFFFFu, pv.y, o);
            }
            if (lane == 0) {
                red[w][eo * 8 + 2 * p]     = pv.x;
                red[w][eo * 8 + 2 * p + 1] = pv.y;
            }
        }
    }
    __syncthreads();
    if (tid < 64) {
        float s = 0.0f;
        #pragma unroll
        for (int ww = 0; ww < 8; ww++) s += red[ww][tid];
        d_H1[b][e0 * 8 + tid] = s;
    }
}

// ---------------------------------------------------------------------------
// Kernel 3: bias projection + final MLP. 16 blocks x 512 threads.
// fc1: 8 thr/out, fc2: 2 thr/out, fc3: 4 thr/out.
// ---------------------------------------------------------------------------
__global__ void __launch_bounds__(512)
mlp_kernel(const float* __restrict__ x, const float* __restrict__ emb,
           const float* __restrict__ emb10,
           const float* __restrict__ fc1w, const float* __restrict__ fc1b,
           const float* __restrict__ fc2w, const float* __restrict__ fc2b,
           const float* __restrict__ fc3w, const float* __restrict__ fc3b,
           float* __restrict__ out) {
    __shared__ __align__(16) float h[1024];
    __shared__ __align__(16) float v1[64];
    __shared__ __align__(16) float v2[256];
    __shared__ float xs[LSEQ];
    __shared__ float Ps[8];
    const int b = blockIdx.x;
    const int tid = threadIdx.x;
    const int w = tid >> 5, lane = tid & 31;

    // P[b,j] = sum_l x[b,l,0] * emb10[l,j]
    xs[tid] = x[(b * LSEQ + tid) * NFEAT];
    __syncthreads();
    if (w < 8) {
        float s = 0.0f;
        #pragma unroll
        for (int i = 0; i < 16; i++)
            s += xs[lane + 32 * i] * emb10[(lane + 32 * i) * 8 + w];
        #pragma unroll
        for (int o = 16; o; o >>= 1) s += __shfl_down_sync(0xFFFFFFFFu, s, o);
        if (lane == 0) Ps[w] = s;
    }
    __syncthreads();

    // h = H1 + emb[e] * P[j]
    #pragma unroll
    for (int k = 0; k < 2; k++) {
        int i = tid + 512 * k;
        h[i] = d_H1[b][i] + emb[i >> 3] * Ps[i & 7];
    }
    __syncthreads();

    // fc1: 64 outputs, 8 threads each
    {
        const int j = tid >> 3, sub = tid & 7;
        const float4* fw = (const float4*)(fc1w + j * 1024);
        const float4* h4 = (const float4*)h;
        float s = 0.0f;
        #pragma unroll
        for (int i = 0; i < 32; i++) {
            float4 a = fw[sub + 8 * i];
            float4 v = h4[sub + 8 * i];
            s += a.x * v.x + a.y * v.y + a.z * v.z + a.w * v.w;
        }
        s += __shfl_down_sync(0xFFFFFFFFu, s, 4, 8);
        s += __shfl_down_sync(0xFFFFFFFFu, s, 2, 8);
        s += __shfl_down_sync(0xFFFFFFFFu, s, 1, 8);
        if (sub == 0) {
            s += fc1b[j];
            v1[j] = s > 0.0f ? s : 0.01f * s;
        }
    }
    __syncthreads();

    // fc2: 256 outputs, 2 threads each
    {
        const int j = tid >> 1, sub = tid & 1;
        const float4* fw = (const float4*)(fc2w + j * 64);
        const float4* v14 = (const float4*)v1;
        float s = 0.0f;
        #pragma unroll
        for (int i = 0; i < 8; i++) {
            float4 a = fw[sub * 8 + i];
            float4 v = v14[sub * 8 + i];
            s += a.x * v.x + a.y * v.y + a.z * v.z + a.w * v.w;
        }
        s += __shfl_down_sync(0xFFFFFFFFu, s, 1, 2);
        if (sub == 0) {
            s += fc2b[j];
            v2[j] = s > 0.0f ? s : 0.01f * s;
        }
    }
    __syncthreads();

    // fc3: 96 outputs, 4 threads each
    if (tid < 384) {
        const int j = tid >> 2, sub = tid & 3;
        const float4* fw = (const float4*)(fc3w + j * 256);
        const float4* v24 = (const float4*)v2;
        float s = 0.0f;
        #pragma unroll
        for (int i = 0; i < 16; i++) {
            float4 a = fw[sub * 16 + i];
            float4 v = v24[sub * 16 + i];
            s += a.x * v.x + a.y * v.y + a.z * v.z + a.w * v.w;
        }
        s += __shfl_down_sync(0xFFFFFFFFu, s, 2, 4);
        s += __shfl_down_sync(0xFFFFFFFFu, s, 1, 4);
        if (sub == 0) out[b * 96 + j] = s + fc3b[j];
    }
}

// ---------------------------------------------------------------------------
extern "C" void kernel_launch(void* const* d_in, const int* in_sizes, int n_in,
                              void* d_out, int out_size) {
    const float* x     = (const float*)d_in[0];
    const float* emb   = (const float*)d_in[1];
    const float* w0    = (const float*)d_in[2];
    const float* b0    = (const float*)d_in[3];
    const float* w1    = (const float*)d_in[4];
    const float* b1    = (const float*)d_in[5];
    const float* w2    = (const float*)d_in[6];
    const float* b2    = (const float*)d_in[7];
    const float* emb10 = (const float*)d_in[8];
    const float* fc1w  = (const float*)d_in[9];
    const float* fc1b  = (const float*)d_in[10];
    const float* fc2w  = (const float*)d_in[11];
    const float* fc2b  = (const float*)d_in[12];
    const float* fc3w  = (const float*)d_in[13];
    const float* fc3b  = (const float*)d_in[14];
    float* out = (float*)d_out;

    prep<<<768, 256>>>(x, emb10);
    gc_gemm<<<dim3(EDIM / 8, NB), 256>>>(emb, w0, b0, w1, b1, w2, b2);
    mlp_kernel<<<NB, 512>>>(x, emb, emb10, fc1w, fc1b, fc2w, fc2b, fc3w, fc3b, out);
}

// round 7
// speedup vs baseline: 1.5896x; 1.1020x over previous
#include <cuda_runtime.h>
#include <math.h>

// Problem constants
#define EDIM   128
#define LSEQ   512
#define NB     16
#define NFEAT  32
#define FBINS  8193
#define LAMBDA 0.01f

// Persistent scratch (device globals)
__device__ __align__(256) float2 d_X[NB][FBINS];   // forward spectrum (ortho)
__device__ __align__(256) float  d_H1[NB][EDIM * 8];
__device__ __align__(256) float  d_TA[FBINS][8];   // irfft+emb10 folded cos table
__device__ __align__(256) float  d_TB[FBINS][8];   // irfft+emb10 folded sin table

// softshrink for v >= 0 (all inputs are relu outputs)
__device__ __forceinline__ float sshrink_nn(float v) {
    return fmaxf(v - LAMBDA, 0.0f);
}

__device__ __forceinline__ unsigned long long fma2(unsigned long long a,
                                                   unsigned long long b,
                                                   unsigned long long c) {
    unsigned long long d;
    asm("fma.rn.f32x2 %0, %1, %2, %3;" : "=l"(d) : "l"(a), "l"(b), "l"(c));
    return d;
}
__device__ __forceinline__ unsigned long long pack2(float v) {
    unsigned long long d;
    asm("mov.b64 %0, {%1, %1};" : "=l"(d) : "f"(v));
    return d;
}
__device__ __forceinline__ float2 unpack2(unsigned long long p) {
    float2 r;
    asm("mov.b64 {%0, %1}, %2;" : "=f"(r.x), "=f"(r.y) : "l"(p));
    return r;
}

__device__ __forceinline__ float2 cmul(float2 a, float2 b) {
    return make_float2(a.x * b.x - a.y * b.y, a.x * b.y + a.y * b.x);
}
__device__ __forceinline__ float2 cadd(float2 a, float2 b) {
    return make_float2(a.x + b.x, a.y + b.y);
}
__device__ __forceinline__ float2 csub(float2 a, float2 b) {
    return make_float2(a.x - b.x, a.y - b.y);
}

// ---------------------------------------------------------------------------
// Kernel 1: PREP. 384 blocks x 256 threads; 2 sub-FFTs per block.
//   fftid = blockIdx*2 + (tid>>7).  fftid<512: forward rfft (r=fftid&31,
//   b=fftid>>5).  fftid>=512: TA/TB tables (idx=fftid-512, r=idx&31, j=idx>>5).
// 512-pt DIT FFT: fused radix-2 stage pairs (5 smem passes, 5 barriers).
// ---------------------------------------------------------------------------
__global__ void __launch_bounds__(256)
prep(const float* __restrict__ x, const float* __restrict__ emb10) {
    __shared__ float2 buf[1024];        // 2 x 512
    __shared__ float2 tw[256];          // e^{-2pi i k/512}
    __shared__ float2 w32[2][32];       // per-sub-FFT e^{-2pi i r q/32}
    const int tid = threadIdx.x;
    const int sub = tid >> 7;
    const int t   = tid & 127;
    const int fftid = blockIdx.x * 2 + sub;
    const bool fwd = (fftid < 512);
    const int idx = fwd ? fftid : fftid - 512;
    const int r = idx & 31;
    float2* B = buf + (sub << 9);

    {
        float s, c;
        sincospif((float)tid * (1.0f / 256.0f), &s, &c);
        tw[tid] = make_float2(c, -s);
    }
    if (t < 32) {
        int ph = (r * t) & 31;
        float s, c;
        sincospif((float)ph * (1.0f / 16.0f), &s, &c);
        w32[sub][t] = make_float2(c, -s);
    }
    __syncthreads();

    // ---- input phase: 4 rows per thread ----
    if (fwd) {
        const int b = idx >> 5;
        #pragma unroll
        for (int li = 0; li < 4; li++) {
            const int l = t + 128 * li;
            const float4* xr4 = (const float4*)(x + (b * LSEQ + l) * NFEAT);
            float sr = 0.0f, si = 0.0f;
            #pragma unroll
            for (int i = 0; i < 8; i++) {
                float4 v4 = xr4[i];
                float2 wa = w32[sub][4 * i + 0], wb = w32[sub][4 * i + 1];
                float2 wc = w32[sub][4 * i + 2], wd = w32[sub][4 * i + 3];
                sr = fmaf(v4.x, wa.x, sr); si = fmaf(v4.x, wa.y, si);
                sr = fmaf(v4.y, wb.x, sr); si = fmaf(v4.y, wb.y, si);
                sr = fmaf(v4.z, wc.x, sr); si = fmaf(v4.z, wc.y, si);
                sr = fmaf(v4.w, wd.x, sr); si = fmaf(v4.w, wd.y, si);
            }
            float ss, cc;
            sincospif((float)(r * l) * (1.0f / 8192.0f), &ss, &cc);
            float yr = fmaf(sr, cc,  si * ss);
            float yi = fmaf(si, cc, -sr * ss);
            B[__brev((unsigned)l) >> 23] = make_float2(yr, yi);
        }
    } else {
        const int j = idx >> 5;
        #pragma unroll
        for (int li = 0; li < 4; li++) {
            const int l = t + 128 * li;
            float ev = emb10[l * 8 + j];
            float ss, cc;
            sincospif((float)(r * l) * (1.0f / 8192.0f), &ss, &cc);
            B[__brev((unsigned)l) >> 23] = make_float2(ev * cc, -ev * ss);
        }
    }
    __syncthreads();

    // ---- fused radix-2 stage pairs: (0,1),(2,3),(4,5),(6,7) ----
    #pragma unroll
    for (int s = 0; s < 8; s += 2) {
        const int half = 1 << s;
        const int j = t & (half - 1);
        const int base = ((t >> s) << (s + 2)) + j;
        float2 a = B[base];
        float2 b = B[base + half];
        float2 c = B[base + 2 * half];
        float2 d = B[base + 3 * half];
        float2 w1 = tw[j << (8 - s)];
        // stage s
        float2 bt = cmul(w1, b);
        float2 dt = cmul(w1, d);
        float2 a1 = cadd(a, bt), b1 = csub(a, bt);
        float2 c1 = cadd(c, dt), d1 = csub(c, dt);
        // stage s+1
        float2 w2a = tw[j << (7 - s)];
        float2 w2b = tw[(j + half) << (7 - s)];
        float2 ct = cmul(w2a, c1);
        float2 dt2 = cmul(w2b, d1);
        B[base]            = cadd(a1, ct);
        B[base + 2 * half] = csub(a1, ct);
        B[base + half]     = cadd(b1, dt2);
        B[base + 3 * half] = csub(b1, dt2);
        __syncthreads();
    }

    // ---- final radix-2 stage s=8 (half=256), 2 butterflies/thread ----
    #pragma unroll
    for (int k = 0; k < 2; k++) {
        int i = t + 128 * k;
        float2 w = tw[i];
        float2 u = B[i];
        float2 v = B[i + 256];
        float2 vt = cmul(w, v);
        B[i]       = cadd(u, vt);
        B[i + 256] = csub(u, vt);
    }
    __syncthreads();

    // ---- output scatter: f = 32t + r ----
    if (fwd) {
        const int b = idx >> 5;
        const float sc = 1.0f / 128.0f;
        #pragma unroll
        for (int k = 0; k < 4; k++) {
            int tt = t + 128 * k;
            int f = 32 * tt + r;
            if (f <= 8192)
                d_X[b][f] = make_float2(B[tt].x * sc, B[tt].y * sc);
        }
    } else {
        const int j = idx >> 5;
        #pragma unroll
        for (int k = 0; k < 4; k++) {
            int tt = t + 128 * k;
            int f = 32 * tt + r;
            if (f <= 8192) {
                float sf = (f == 0 || f == 8192) ? (1.0f / 128.0f) : (2.0f / 128.0f);
                d_TA[f][j] = sf * B[tt].x;
                d_TB[f][j] = sf * B[tt].y;
            }
        }
    }
}

// ---------------------------------------------------------------------------
// Kernel 2: fused fourierGC + (irfft . emb10) contraction. Packed f32x2 accs,
// branchless non-negative softshrink.
// ---------------------------------------------------------------------------
__global__ void __launch_bounds__(256, 1)
gc_gemm(const float* __restrict__ emb,
        const float* __restrict__ w0, const float* __restrict__ b0,
        const float* __restrict__ w1, const float* __restrict__ b1,
        const float* __restrict__ w2, const float* __restrict__ b2) {
    const int e0 = blockIdx.x * 8;
    const int b  = blockIdx.y;
    const int tid = threadIdx.x;

    float D00[8], D01[8], C00[8], C01[8];
    float d10[8], d11[8], C10[8], C11[8];
    float d20[8], d21[8], C20[8], C21[8];
    #pragma unroll
    for (int eo = 0; eo < 8; eo++) {
        int e = e0 + eo;
        float em = emb[e];
        D00[eo] = em * w0[e * 129];  D01[eo] = em * w0[16384 + e * 129];
        C00[eo] = b0[e];             C01[eo] = b0[128 + e];
        d10[eo] = w1[e * 129];       d11[eo] = w1[16384 + e * 129];
        C10[eo] = b1[e];             C11[eo] = b1[128 + e];
        d20[eo] = w2[e * 129];       d21[eo] = w2[16384 + e * 129];
        C20[eo] = b2[e];             C21[eo] = b2[128 + e];
    }

    unsigned long long acc2[8][4];
    #pragma unroll
    for (int eo = 0; eo < 8; eo++)
        #pragma unroll
        for (int p = 0; p < 4; p++) acc2[eo][p] = 0ull;

    for (int f = tid; f < FBINS; f += 256) {
        float2 X = d_X[b][f];
        float xr = X.x, xi = X.y;
        const ulonglong2* taP = (const ulonglong2*)d_TA[f];
        const ulonglong2* tbP = (const ulonglong2*)d_TB[f];
        ulonglong2 taL = taP[0], taH = taP[1];
        ulonglong2 tbL = tbP[0], tbH = tbP[1];
        #pragma unroll
        for (int eo = 0; eo < 8; eo++) {
            float or1 = fmaxf(fmaf(xr, D00[eo], fmaf(-xi, D01[eo], C00[eo])), 0.0f);
            float oi1 = fmaxf(fmaf(xi, D00[eo], fmaf( xr, D01[eo], C01[eo])), 0.0f);
            float pr = sshrink_nn(or1), pi = sshrink_nn(oi1);
            float or2 = fmaxf(fmaf(or1, d10[eo], fmaf(-oi1, d11[eo], C10[eo])), 0.0f);
            float oi2 = fmaxf(fmaf(oi1, d10[eo], fmaf( or2, d11[eo], C11[eo])), 0.0f);
            pr += sshrink_nn(or2); pi += sshrink_nn(oi2);
            float or3 = fmaxf(fmaf(or2, d20[eo], fmaf(-oi2, d21[eo], C20[eo])), 0.0f);
            float oi3 = fmaxf(fmaf(oi2, d20[eo], fmaf( or3, d21[eo], C21[eo])), 0.0f);
            unsigned long long zr2 = pack2(sshrink_nn(or3) + pr);
            unsigned long long zi2 = pack2(sshrink_nn(oi3) + pi);
            acc2[eo][0] = fma2(zr2, taL.x, fma2(zi2, tbL.x, acc2[eo][0]));
            acc2[eo][1] = fma2(zr2, taL.y, fma2(zi2, tbL.y, acc2[eo][1]));
            acc2[eo][2] = fma2(zr2, taH.x, fma2(zi2, tbH.x, acc2[eo][2]));
            acc2[eo][3] = fma2(zr2, taH.y, fma2(zi2, tbH.y, acc2[eo][3]));
        }
    }

    __shared__ float red[8][64];
    const int lane = tid & 31, w = tid >> 5;
    #pragma unroll
    for (int eo = 0; eo < 8; eo++) {
        #pragma unroll
        for (int p = 0; p < 4; p++) {
            float2 pv = unpack2(acc2[eo][p]);
            #pragma unroll
            for (int o = 16; o; o >>= 1) {
                pv.x += __shfl_down_sync(0xFFFFFFFFu, pv.x, o);
                pv.y += __shfl_down_sync(0xFFFFFFFFu, pv.y, o);
            }
            if (lane == 0) {
                red[w][eo * 8 + 2 * p]     = pv.x;
                red[w][eo * 8 + 2 * p + 1] = pv.y;
            }
        }
    }
    __syncthreads();
    if (tid < 64) {
        float s = 0.0f;
        #pragma unroll
        for (int ww = 0; ww < 8; ww++) s += red[ww][tid];
        d_H1[b][e0 * 8 + tid] = s;
    }
}

// ---------------------------------------------------------------------------
// Kernel 3: bias projection + final MLP. 16 blocks x 512 threads.
// ---------------------------------------------------------------------------
__global__ void __launch_bounds__(512)
mlp_kernel(const float* __restrict__ x, const float* __restrict__ emb,
           const float* __restrict__ emb10,
           const float* __restrict__ fc1w, const float* __restrict__ fc1b,
           const float* __restrict__ fc2w, const float* __restrict__ fc2b,
           const float* __restrict__ fc3w, const float* __restrict__ fc3b,
           float* __restrict__ out) {
    __shared__ __align__(16) float h[1024];
    __shared__ __align__(16) float v1[64];
    __shared__ __align__(16) float v2[256];
    __shared__ float xs[LSEQ];
    __shared__ float Ps[8];
    const int b = blockIdx.x;
    const int tid = threadIdx.x;
    const int w = tid >> 5, lane = tid & 31;

    xs[tid] = x[(b * LSEQ + tid) * NFEAT];
    __syncthreads();
    if (w < 8) {
        float s = 0.0f;
        #pragma unroll
        for (int i = 0; i < 16; i++)
            s += xs[lane + 32 * i] * emb10[(lane + 32 * i) * 8 + w];
        #pragma unroll
        for (int o = 16; o; o >>= 1) s += __shfl_down_sync(0xFFFFFFFFu, s, o);
        if (lane == 0) Ps[w] = s;
    }
    __syncthreads();

    #pragma unroll
    for (int k = 0; k < 2; k++) {
        int i = tid + 512 * k;
        h[i] = d_H1[b][i] + emb[i >> 3] * Ps[i & 7];
    }
    __syncthreads();

    // fc1: 64 outputs, 8 threads each
    {
        const int j = tid >> 3, sub = tid & 7;
        const float4* fw = (const float4*)(fc1w + j * 1024);
        const float4* h4 = (const float4*)h;
        float s = 0.0f;
        #pragma unroll
        for (int i = 0; i < 32; i++) {
            float4 a = fw[sub + 8 * i];
            float4 v = h4[sub + 8 * i];
            s += a.x * v.x + a.y * v.y + a.z * v.z + a.w * v.w;
        }
        s += __shfl_down_sync(0xFFFFFFFFu, s, 4, 8);
        s += __shfl_down_sync(0xFFFFFFFFu, s, 2, 8);
        s += __shfl_down_sync(0xFFFFFFFFu, s, 1, 8);
        if (sub == 0) {
            s += fc1b[j];
            v1[j] = s > 0.0f ? s : 0.01f * s;
        }
    }
    __syncthreads();

    // fc2: 256 outputs, 2 threads each
    {
        const int j = tid >> 1, sub = tid & 1;
        const float4* fw = (const float4*)(fc2w + j * 64);
        const float4* v14 = (const float4*)v1;
        float s = 0.0f;
        #pragma unroll
        for (int i = 0; i < 8; i++) {
            float4 a = fw[sub * 8 + i];
            float4 v = v14[sub * 8 + i];
            s += a.x * v.x + a.y * v.y + a.z * v.z + a.w * v.w;
        }
        s += __shfl_down_sync(0xFFFFFFFFu, s, 1, 2);
        if (sub == 0) {
            s += fc2b[j];
            v2[j] = s > 0.0f ? s : 0.01f * s;
        }
    }
    __syncthreads();

    // fc3: 96 outputs, 4 threads each
    if (tid < 384) {
        const int j = tid >> 2, sub = tid & 3;
        const float4* fw = (const float4*)(fc3w + j * 256);
        const float4* v24 = (const float4*)v2;
        float s = 0.0f;
        #pragma unroll
        for (int i = 0; i < 16; i++) {
            float4 a = fw[sub * 16 + i];
            float4 v = v24[sub * 16 + i];
            s += a.x * v.x + a.y * v.y + a.z * v.z + a.w * v.w;
        }
        s += __shfl_down_sync(0xFFFFFFFFu, s, 2, 4);
        s += __shfl_down_sync(0xFFFFFFFFu, s, 1, 4);
        if (sub == 0) out[b * 96 + j] = s + fc3b[j];
    }
}

// ---------------------------------------------------------------------------
extern "C" void kernel_launch(void* const* d_in, const int* in_sizes, int n_in,
                              void* d_out, int out_size) {
    const float* x     = (const float*)d_in[0];
    const float* emb   = (const float*)d_in[1];
    const float* w0    = (const float*)d_in[2];
    const float* b0    = (const float*)d_in[3];
    const float* w1    = (const float*)d_in[4];
    const float* b1    = (const float*)d_in[5];
    const float* w2    = (const float*)d_in[6];
    const float* b2    = (const float*)d_in[7];
    const float* emb10 = (const float*)d_in[8];
    const float* fc1w  = (const float*)d_in[9];
    const float* fc1b  = (const float*)d_in[10];
    const float* fc2w  = (const float*)d_in[11];
    const float* fc2b  = (const float*)d_in[12];
    const float* fc3w  = (const float*)d_in[13];
    const float* fc3b  = (const float*)d_in[14];
    float* out = (float*)d_out;

    prep<<<384, 256>>>(x, emb10);
    gc_gemm<<<dim3(EDIM / 8, NB), 256>>>(emb, w0, b0, w1, b1, w2, b2);
    mlp_kernel<<<NB, 512>>>(x, emb, emb10, fc1w, fc1b, fc2w, fc2b, fc3w, fc3b, out);
}

// round 8
// speedup vs baseline: 1.8228x; 1.1467x over previous
#include <cuda_runtime.h>
#include <math.h>

#define EDIM   128
#define LSEQ   512
#define NB     16
#define NFEAT  32
#define NBINS  8193
#define LAMBDA 0.01f

typedef unsigned long long u64;

// Persistent scratch. Index p is the PERMUTED bin order (DIF slot order):
// p = r*256 + m  holds f = 32*rev9(2m) + r ;  p = 8192 holds f = 8192.
// gc_gemm only ever sums over all bins, so the order is irrelevant as long
// as d_X and d_TA/d_TB agree (they do: identical FFT structure).
__device__ __align__(256) float2 d_X[NB][8200];
__device__ __align__(256) float  d_H1[NB][EDIM * 8];
__device__ __align__(256) float  d_TA[8200][8];
__device__ __align__(256) float  d_TB[8200][8];

// ---- packed f32x2 helpers ----
__device__ __forceinline__ u64 fma2(u64 a, u64 b, u64 c) {
    u64 d; asm("fma.rn.f32x2 %0, %1, %2, %3;" : "=l"(d) : "l"(a), "l"(b), "l"(c));
    return d;
}
__device__ __forceinline__ u64 add2(u64 a, u64 b) {
    u64 d; asm("add.rn.f32x2 %0, %1, %2;" : "=l"(d) : "l"(a), "l"(b));
    return d;
}
__device__ __forceinline__ u64 pack2(float v) {
    u64 d; asm("mov.b64 %0, {%1, %1};" : "=l"(d) : "f"(v)); return d;
}
__device__ __forceinline__ u64 packpair(float a, float b) {
    u64 d; asm("mov.b64 %0, {%1, %2};" : "=l"(d) : "f"(a), "f"(b)); return d;
}
__device__ __forceinline__ float2 unpack2(u64 p) {
    float2 r; asm("mov.b64 {%0, %1}, %2;" : "=f"(r.x), "=f"(r.y) : "l"(p));
    return r;
}
__device__ __forceinline__ u64 relu2(u64 v) {
    float2 u = unpack2(v);
    return packpair(fmaxf(u.x, 0.0f), fmaxf(u.y, 0.0f));
}

__device__ __forceinline__ float2 cmul(float2 a, float2 b) {
    return make_float2(a.x * b.x - a.y * b.y, a.x * b.y + a.y * b.x);
}
__device__ __forceinline__ float2 cadd(float2 a, float2 b) {
    return make_float2(a.x + b.x, a.y + b.y);
}
__device__ __forceinline__ float2 csub(float2 a, float2 b) {
    return make_float2(a.x - b.x, a.y - b.y);
}

#define PAD(i) ((i) + ((i) >> 4))

// ---------------------------------------------------------------------------
// Kernel 1: PREP. 384 blocks x 256 threads, 2 sub-FFTs per block.
// DIF 512-pt FFT (natural input -> bit-reversed slots), padded smem.
//   fftid < 512 : forward rfft  (r = fftid&31, b = fftid>>5)
//   fftid >= 512: TA/TB tables  (idx = fftid-512, r = idx&31, j = idx>>5)
// Store even slots k=2m at p = r*256+m (coalesced); slot 1 (f=8192) at p=8192.
// ---------------------------------------------------------------------------
__global__ void __launch_bounds__(256)
prep(const float* __restrict__ x, const float* __restrict__ emb10) {
    __shared__ float2 buf[2][546];
    __shared__ float2 tw[256];          // e^{-2pi i k/512}
    __shared__ float2 w32[2][32];       // e^{-2pi i r q/32} (fwd path)
    const int tid = threadIdx.x;
    const int sub = tid >> 7;
    const int t   = tid & 127;
    const int fftid = blockIdx.x * 2 + sub;
    const bool fwd = (fftid < 512);
    const int idx = fwd ? fftid : fftid - 512;
    const int r = idx & 31;
    float2* B = buf[sub];

    {
        float s, c;
        sincospif((float)tid * (1.0f / 256.0f), &s, &c);
        tw[tid] = make_float2(c, -s);
    }
    if (t < 32) {
        int ph = (r * t) & 31;
        float s, c;
        sincospif((float)ph * (1.0f / 16.0f), &s, &c);
        w32[sub][t] = make_float2(c, -s);
    }
    __syncthreads();

    // ---- input phase (natural order, conflict-free stores) ----
    if (fwd) {
        const int b = idx >> 5;
        #pragma unroll
        for (int li = 0; li < 4; li++) {
            const int l = t + 128 * li;
            const float4* xr4 = (const float4*)(x + (b * LSEQ + l) * NFEAT);
            float sr = 0.0f, si = 0.0f;
            #pragma unroll
            for (int i = 0; i < 8; i++) {
                float4 v4 = xr4[i];
                float2 wa = w32[sub][4 * i + 0], wb = w32[sub][4 * i + 1];
                float2 wc = w32[sub][4 * i + 2], wd = w32[sub][4 * i + 3];
                sr = fmaf(v4.x, wa.x, sr); si = fmaf(v4.x, wa.y, si);
                sr = fmaf(v4.y, wb.x, sr); si = fmaf(v4.y, wb.y, si);
                sr = fmaf(v4.z, wc.x, sr); si = fmaf(v4.z, wc.y, si);
                sr = fmaf(v4.w, wd.x, sr); si = fmaf(v4.w, wd.y, si);
            }
            float ss, cc;
            sincospif((float)(r * l) * (1.0f / 8192.0f), &ss, &cc);
            B[PAD(l)] = make_float2(fmaf(sr, cc, si * ss), fmaf(si, cc, -sr * ss));
        }
    } else {
        const int j = idx >> 5;
        #pragma unroll
        for (int li = 0; li < 4; li++) {
            const int l = t + 128 * li;
            float ev = emb10[l * 8 + j];
            float ss, cc;
            sincospif((float)(r * l) * (1.0f / 8192.0f), &ss, &cc);
            B[PAD(l)] = make_float2(ev * cc, -ev * ss);
        }
    }
    __syncthreads();

    // ---- DIF fused stage pairs: (8,7),(6,5),(4,3),(2,1) ----
    #pragma unroll
    for (int s = 8; s >= 2; s -= 2) {
        const int h = 1 << s, h2 = h >> 1;
        const int j = t & (h2 - 1);
        const int base = ((t >> (s - 1)) << (s + 1)) + j;
        float2 a  = B[PAD(base)];
        float2 bb = B[PAD(base + h2)];
        float2 c  = B[PAD(base + h)];
        float2 d  = B[PAD(base + h + h2)];
        // stage s: pairs (a,c) and (bb,d), twiddle e^{-2pi i j'/2h}
        float2 wA = tw[j << (8 - s)];
        float2 wB = tw[(j + h2) << (8 - s)];
        float2 a1 = cadd(a, c),  c1 = cmul(csub(a, c),  wA);
        float2 b1 = cadd(bb, d), d1 = cmul(csub(bb, d), wB);
        // stage s-1: pairs (a1,b1) and (c1,d1), twiddle e^{-2pi i j/h}
        float2 w2 = tw[j << (9 - s)];
        B[PAD(base)]          = cadd(a1, b1);
        B[PAD(base + h2)]     = cmul(csub(a1, b1), w2);
        B[PAD(base + h)]      = cadd(c1, d1);
        B[PAD(base + h + h2)] = cmul(csub(c1, d1), w2);
        __syncthreads();
    }
    // ---- final stage s=0 (w=1) ----
    #pragma unroll
    for (int k = 0; k < 2; k++) {
        int i = t + 128 * k;
        float2 u = B[PAD(2 * i)];
        float2 v = B[PAD(2 * i + 1)];
        B[PAD(2 * i)]     = cadd(u, v);
        B[PAD(2 * i + 1)] = csub(u, v);
    }
    __syncthreads();

    // ---- output: even slots -> p = r*256+m (coalesced); slot 1 -> p=8192 ----
    if (fwd) {
        const int b = idx >> 5;
        const float sc = 1.0f / 128.0f;
        #pragma unroll
        for (int k = 0; k < 2; k++) {
            int m = t + 128 * k;
            float2 v = B[PAD(2 * m)];
            d_X[b][r * 256 + m] = make_float2(v.x * sc, v.y * sc);
        }
        if (r == 0 && t == 0) {
            float2 v = B[PAD(1)];
            d_X[b][8192] = make_float2(v.x * sc, v.y * sc);
        }
    } else {
        const int j = idx >> 5;
        #pragma unroll
        for (int k = 0; k < 2; k++) {
            int m = t + 128 * k;
            int p = r * 256 + m;
            float sf = (p == 0) ? (1.0f / 128.0f) : (2.0f / 128.0f);
            float2 v = B[PAD(2 * m)];
            d_TA[p][j] = sf * v.x;
            d_TB[p][j] = sf * v.y;
        }
        if (r == 0 && t == 0) {
            float2 v = B[PAD(1)];
            d_TA[8192][j] = (1.0f / 128.0f) * v.x;
            d_TB[8192][j] = (1.0f / 128.0f) * v.y;
        }
    }
}

// ---------------------------------------------------------------------------
// Kernel 2: fused fourierGC + (irfft . emb10). e-pair packed f32x2 chain,
// 4 e + 2 b per block. Grid (32, 8) x 256 threads.
// ---------------------------------------------------------------------------
__global__ void __launch_bounds__(256)
gc_gemm(const float* __restrict__ emb,
        const float* __restrict__ w0, const float* __restrict__ b0,
        const float* __restrict__ w1, const float* __restrict__ b1,
        const float* __restrict__ w2, const float* __restrict__ b2) {
    const int e0  = blockIdx.x * 4;
    const int b0i = blockIdx.y * 2;
    const int tid = threadIdx.x;

    u64 pD00[2], pD01[2], pD01n[2], pC00[2], pC01[2];
    u64 pd10[2], pd11[2], pd11n[2], pC10[2], pC11[2];
    u64 pd20[2], pd21[2], pd21n[2], pC20[2], pC21[2];
    #pragma unroll
    for (int pp = 0; pp < 2; pp++) {
        int eA = e0 + 2 * pp, eB = eA + 1;
        float emA = emb[eA], emB = emb[eB];
        float a01 = emA * w0[16384 + eA * 129], q01 = emB * w0[16384 + eB * 129];
        pD00[pp]  = packpair(emA * w0[eA * 129], emB * w0[eB * 129]);
        pD01[pp]  = packpair(a01, q01);
        pD01n[pp] = packpair(-a01, -q01);
        pC00[pp]  = packpair(b0[eA], b0[eB]);
        pC01[pp]  = packpair(b0[128 + eA], b0[128 + eB]);
        float a11 = w1[16384 + eA * 129], q11 = w1[16384 + eB * 129];
        pd10[pp]  = packpair(w1[eA * 129], w1[eB * 129]);
        pd11[pp]  = packpair(a11, q11);
        pd11n[pp] = packpair(-a11, -q11);
        pC10[pp]  = packpair(b1[eA], b1[eB]);
        pC11[pp]  = packpair(b1[128 + eA], b1[128 + eB]);
        float a21 = w2[16384 + eA * 129], q21 = w2[16384 + eB * 129];
        pd20[pp]  = packpair(w2[eA * 129], w2[eB * 129]);
        pd21[pp]  = packpair(a21, q21);
        pd21n[pp] = packpair(-a21, -q21);
        pC20[pp]  = packpair(b2[eA], b2[eB]);
        pC21[pp]  = packpair(b2[128 + eA], b2[128 + eB]);
    }
    const u64 NL = pack2(-LAMBDA);

    u64 acc[2][4][4];   // [bb][eo][j-pair], packed over j
    #pragma unroll
    for (int bb = 0; bb < 2; bb++)
        #pragma unroll
        for (int eo = 0; eo < 4; eo++)
            #pragma unroll
            for (int jp = 0; jp < 4; jp++) acc[bb][eo][jp] = 0ull;

    for (int p = tid; p < NBINS; p += 256) {
        float2 X0 = d_X[b0i][p];
        float2 X1 = d_X[b0i + 1][p];
        ulonglong2 taL = *(const ulonglong2*)&d_TA[p][0];
        ulonglong2 taH = *(const ulonglong2*)&d_TA[p][4];
        ulonglong2 tbL = *(const ulonglong2*)&d_TB[p][0];
        ulonglong2 tbH = *(const ulonglong2*)&d_TB[p][4];
        #pragma unroll
        for (int bb = 0; bb < 2; bb++) {
            u64 xr2 = pack2(bb ? X1.x : X0.x);
            u64 xi2 = pack2(bb ? X1.y : X0.y);
            #pragma unroll
            for (int pp = 0; pp < 2; pp++) {
                u64 r1r = fma2(xr2, pD00[pp], fma2(xi2, pD01n[pp], pC00[pp]));
                u64 o1r = relu2(r1r);
                u64 r1i = fma2(xi2, pD00[pp], fma2(xr2, pD01[pp], pC01[pp]));
                u64 o1i = relu2(r1i);
                u64 pr = relu2(add2(r1r, NL));
                u64 pi = relu2(add2(r1i, NL));
                u64 r2r = fma2(o1r, pd10[pp], fma2(o1i, pd11n[pp], pC10[pp]));
                u64 o2r = relu2(r2r);
                u64 r2i = fma2(o1i, pd10[pp], fma2(o2r, pd11[pp], pC11[pp]));
                u64 o2i = relu2(r2i);
                pr = add2(pr, relu2(add2(r2r, NL)));
                pi = add2(pi, relu2(add2(r2i, NL)));
                u64 r3r = fma2(o2r, pd20[pp], fma2(o2i, pd21n[pp], pC20[pp]));
                u64 o3r = relu2(r3r);
                u64 r3i = fma2(o2i, pd20[pp], fma2(o3r, pd21[pp], pC21[pp]));
                u64 zr2 = add2(pr, relu2(add2(r3r, NL)));
                u64 zi2 = add2(pi, relu2(add2(r3i, NL)));
                float2 zrv = unpack2(zr2), ziv = unpack2(zi2);
                {
                    u64 zr = pack2(zrv.x), zi = pack2(ziv.x);
                    u64* A = acc[bb][2 * pp];
                    A[0] = fma2(zr, taL.x, fma2(zi, tbL.x, A[0]));
                    A[1] = fma2(zr, taL.y, fma2(zi, tbL.y, A[1]));
                    A[2] = fma2(zr, taH.x, fma2(zi, tbH.x, A[2]));
                    A[3] = fma2(zr, taH.y, fma2(zi, tbH.y, A[3]));
                }
                {
                    u64 zr = pack2(zrv.y), zi = pack2(ziv.y);
                    u64* A = acc[bb][2 * pp + 1];
                    A[0] = fma2(zr, taL.x, fma2(zi, tbL.x, A[0]));
                    A[1] = fma2(zr, taL.y, fma2(zi, tbL.y, A[1]));
                    A[2] = fma2(zr, taH.x, fma2(zi, tbH.x, A[2]));
                    A[3] = fma2(zr, taH.y, fma2(zi, tbH.y, A[3]));
                }
            }
        }
    }

    __shared__ float red[8][64];
    const int lane = tid & 31, w = tid >> 5;
    #pragma unroll
    for (int bb = 0; bb < 2; bb++) {
        #pragma unroll
        for (int eo = 0; eo < 4; eo++) {
            #pragma unroll
            for (int jp = 0; jp < 4; jp++) {
                float2 pv = unpack2(acc[bb][eo][jp]);
                #pragma unroll
                for (int o = 16; o; o >>= 1) {
                    pv.x += __shfl_down_sync(0xFFFFFFFFu, pv.x, o);
                    pv.y += __shfl_down_sync(0xFFFFFFFFu, pv.y, o);
                }
                if (lane == 0) {
                    red[w][bb * 32 + eo * 8 + 2 * jp]     = pv.x;
                    red[w][bb * 32 + eo * 8 + 2 * jp + 1] = pv.y;
                }
            }
        }
        __syncwarp();
    }
    __syncthreads();
    if (tid < 64) {
        float s = 0.0f;
        #pragma unroll
        for (int ww = 0; ww < 8; ww++) s += red[ww][tid];
        d_H1[b0i + (tid >> 5)][e0 * 8 + (tid & 31)] = s;
    }
}

// ---------------------------------------------------------------------------
// Kernel 3: bias projection + final MLP. 16 blocks x 512 threads.
// ---------------------------------------------------------------------------
__global__ void __launch_bounds__(512)
mlp_kernel(const float* __restrict__ x, const float* __restrict__ emb,
           const float* __restrict__ emb10,
           const float* __restrict__ fc1w, const float* __restrict__ fc1b,
           const float* __restrict__ fc2w, const float* __restrict__ fc2b,
           const float* __restrict__ fc3w, const float* __restrict__ fc3b,
           float* __restrict__ out) {
    __shared__ __align__(16) float h[1024];
    __shared__ __align__(16) float v1[64];
    __shared__ __align__(16) float v2[256];
    __shared__ float xs[LSEQ];
    __shared__ float Ps[8];
    const int b = blockIdx.x;
    const int tid = threadIdx.x;
    const int w = tid >> 5, lane = tid & 31;

    xs[tid] = x[(b * LSEQ + tid) * NFEAT];
    __syncthreads();
    if (w < 8) {
        float s = 0.0f;
        #pragma unroll
        for (int i = 0; i < 16; i++)
            s += xs[lane + 32 * i] * emb10[(lane + 32 * i) * 8 + w];
        #pragma unroll
        for (int o = 16; o; o >>= 1) s += __shfl_down_sync(0xFFFFFFFFu, s, o);
        if (lane == 0) Ps[w] = s;
    }
    __syncthreads();

    #pragma unroll
    for (int k = 0; k < 2; k++) {
        int i = tid + 512 * k;
        h[i] = d_H1[b][i] + emb[i >> 3] * Ps[i & 7];
    }
    __syncthreads();

    {
        const int j = tid >> 3, sub = tid & 7;
        const float4* fw = (const float4*)(fc1w + j * 1024);
        const float4* h4 = (const float4*)h;
        float s = 0.0f;
        #pragma unroll
        for (int i = 0; i < 32; i++) {
            float4 a = fw[sub + 8 * i];
            float4 v = h4[sub + 8 * i];
            s += a.x * v.x + a.y * v.y + a.z * v.z + a.w * v.w;
        }
        s += __shfl_down_sync(0xFFFFFFFFu, s, 4, 8);
        s += __shfl_down_sync(0xFFFFFFFFu, s, 2, 8);
        s += __shfl_down_sync(0xFFFFFFFFu, s, 1, 8);
        if (sub == 0) {
            s += fc1b[j];
            v1[j] = s > 0.0f ? s : 0.01f * s;
        }
    }
    __syncthreads();

    {
        const int j = tid >> 1, sub = tid & 1;
        const float4* fw = (const float4*)(fc2w + j * 64);
        const float4* v14 = (const float4*)v1;
        float s = 0.0f;
        #pragma unroll
        for (int i = 0; i < 8; i++) {
            float4 a = fw[sub * 8 + i];
            float4 v = v14[sub * 8 + i];
            s += a.x * v.x + a.y * v.y + a.z * v.z + a.w * v.w;
        }
        s += __shfl_down_sync(0xFFFFFFFFu, s, 1, 2);
        if (sub == 0) {
            s += fc2b[j];
            v2[j] = s > 0.0f ? s : 0.01f * s;
        }
    }
    __syncthreads();

    if (tid < 384) {
        const int j = tid >> 2, sub = tid & 3;
        const float4* fw = (const float4*)(fc3w + j * 256);
        const float4* v24 = (const float4*)v2;
        float s = 0.0f;
        #pragma unroll
        for (int i = 0; i < 16; i++) {
            float4 a = fw[sub * 16 + i];
            float4 v = v24[sub * 16 + i];
            s += a.x * v.x + a.y * v.y + a.z * v.z + a.w * v.w;
        }
        s += __shfl_down_sync(0xFFFFFFFFu, s, 2, 4);
        s += __shfl_down_sync(0xFFFFFFFFu, s, 1, 4);
        if (sub == 0) out[b * 96 + j] = s + fc3b[j];
    }
}

// ---------------------------------------------------------------------------
extern "C" void kernel_launch(void* const* d_in, const int* in_sizes, int n_in,
                              void* d_out, int out_size) {
    const float* x     = (const float*)d_in[0];
    const float* emb   = (const float*)d_in[1];
    const float* w0    = (const float*)d_in[2];
    const float* b0    = (const float*)d_in[3];
    const float* w1    = (const float*)d_in[4];
    const float* b1    = (const float*)d_in[5];
    const float* w2    = (const float*)d_in[6];
    const float* b2    = (const float*)d_in[7];
    const float* emb10 = (const float*)d_in[8];
    const float* fc1w  = (const float*)d_in[9];
    const float* fc1b  = (const float*)d_in[10];
    const float* fc2w  = (const float*)d_in[11];
    const float* fc2b  = (const float*)d_in[12];
    const float* fc3w  = (const float*)d_in[13];
    const float* fc3b  = (const float*)d_in[14];
    float* out = (float*)d_out;

    prep<<<384, 256>>>(x, emb10);
    gc_gemm<<<dim3(32, 8), 256>>>(emb, w0, b0, w1, b1, w2, b2);
    mlp_kernel<<<NB, 512>>>(x, emb, emb10, fc1w, fc1b, fc2w, fc2b, fc3w, fc3b, out);
}